// round 6
// baseline (speedup 1.0000x reference)
#include <cuda_runtime.h>
#include <cuda_bf16.h>
#include <cstdint>

#define NN 100000
#define NE 1000000
#define SLOT 128
#define EP 68          // smem row pitch (floats) for h tiles in k_proj
#define WP 72          // W smem row pitch with half-row shift (k_proj)

// ---------------- scratch (static device globals; no allocation) ----------------
__device__ float g_A1h[NN * 64];
__device__ float g_A2h[NN * 64];
__device__ float g_B1h[NN * 64];
__device__ float g_B2h[NN * 64];
__device__ int g_deg[NN];
__device__ int g_slot_eid[NN * SLOT];
__device__ int g_slot_src[NN * SLOT];
__device__ __align__(16) unsigned short g_WT_hi[64 * 64];   // B3w^T bf16 hi  [n][k]
__device__ __align__(16) unsigned short g_WT_lo[64 * 64];   // B3w^T bf16 lo  [n][k]

typedef unsigned long long ull;

static __device__ __forceinline__ ull splat2(float x) {
    ull r; asm("mov.b64 %0, {%1, %1};" : "=l"(r) : "f"(x)); return r;
}
static __device__ __forceinline__ void fma2(ull &c, ull a, ull b) {
    asm("fma.rn.f32x2 %0, %1, %2, %3;" : "=l"(c) : "l"(a), "l"(b), "l"(c));
}
static __device__ __forceinline__ float2 unpk(ull v) {
    float2 f; asm("mov.b64 {%0, %1}, %2;" : "=f"(f.x), "=f"(f.y) : "l"(v)); return f;
}
static __device__ __forceinline__ int wofs(int k, int c4) {
    return k * WP + c4 + ((c4 & 32) >> 3);
}
static __device__ __forceinline__ void cvt_hilo(float x, unsigned short &hi, unsigned short &lo) {
    __nv_bfloat16 h = __float2bfloat16(x);
    float r = x - __bfloat162float(h);
    __nv_bfloat16 l = __float2bfloat16(r);
    hi = *reinterpret_cast<unsigned short*>(&h);
    lo = *reinterpret_cast<unsigned short*>(&l);
}
static __device__ __forceinline__ void mma16816(float* c, uint32_t a0, uint32_t a1,
                                                uint32_t a2, uint32_t a3,
                                                uint32_t b0, uint32_t b1) {
    asm volatile(
        "mma.sync.aligned.m16n8k16.row.col.f32.bf16.bf16.f32 "
        "{%0,%1,%2,%3}, {%4,%5,%6,%7}, {%8,%9}, {%0,%1,%2,%3};"
        : "+f"(c[0]), "+f"(c[1]), "+f"(c[2]), "+f"(c[3])
        : "r"(a0), "r"(a1), "r"(a2), "r"(a3), "r"(b0), "r"(b1));
}

// ---------------- K1: node projections (fp32 FFMA2 path, round-3 style) ---------
#define PROJ_SMEM ((4 * 64 * WP + 64 * EP + 256) * 4)

__global__ void __launch_bounds__(256, 2) k_proj(
    const float* __restrict__ h,
    const float* __restrict__ A1w, const float* __restrict__ A1b,
    const float* __restrict__ A2w, const float* __restrict__ A2b,
    const float* __restrict__ B1w, const float* __restrict__ B1b,
    const float* __restrict__ B2w, const float* __restrict__ B2b)
{
    extern __shared__ float sm[];
    float* Wsm = sm;
    float* hsm = sm + 4 * 64 * WP;
    float* bsm = hsm + 64 * EP;

    int tid = threadIdx.x;
    int nb0 = blockIdx.x * 64;

    const float* Ws[4] = {A1w, A2w, B1w, B2w};
    #pragma unroll
    for (int m = 0; m < 4; m++) {
        float* Wm = Wsm + m * 64 * WP;
        for (int i = tid; i < 1024; i += 256) {
            int k = i >> 4, c4 = 4 * (i & 15);
            *(float4*)&Wm[wofs(k, c4)] = ((const float4*)Ws[m])[i];
        }
    }
    {
        const float* Bs[4] = {A1b, A2b, B1b, B2b};
        bsm[tid] = Bs[tid >> 6][tid & 63];
    }
    for (int i = tid; i < 64 * 16; i += 256) {
        int r = i >> 4, p = i & 15;
        int node = nb0 + r;
        float4 v = make_float4(0.f, 0.f, 0.f, 0.f);
        if (node < NN) v = ((const float4*)h)[node * 16 + p];
        *(float4*)&hsm[r * EP + 4 * p] = v;
    }
    if (tid < 64 && nb0 + tid < NN) g_deg[nb0 + tid] = 0;
    __syncthreads();

    int m = tid >> 6;
    int wloc = (tid >> 5) & 1;
    int lane = tid & 31;
    int g = lane >> 3, cg = lane & 7;
    int c0 = 8 * cg;
    int c0s = c0 + ((c0 & 32) >> 3);
    int rb = 32 * wloc + g;
    const float* Wm = Wsm + m * 64 * WP;

    ull acc[8][4];
    #pragma unroll
    for (int j = 0; j < 8; j++)
        #pragma unroll
        for (int c = 0; c < 4; c++) acc[j][c] = 0ull;

    #pragma unroll 2
    for (int k4 = 0; k4 < 16; k4++) {
        float4 a[8];
        #pragma unroll
        for (int j = 0; j < 8; j++)
            a[j] = *(const float4*)&hsm[(rb + 4 * j) * EP + 4 * k4];
        #pragma unroll
        for (int kk = 0; kk < 4; kk++) {
            const float* wr = &Wm[(4 * k4 + kk) * WP];
            ulonglong2 wA = *(const ulonglong2*)&wr[c0s];
            ulonglong2 wB = *(const ulonglong2*)&wr[c0s + 4];
            #pragma unroll
            for (int j = 0; j < 8; j++) {
                float av = (kk == 0) ? a[j].x : (kk == 1) ? a[j].y : (kk == 2) ? a[j].z : a[j].w;
                ull ax = splat2(av);
                fma2(acc[j][0], ax, wA.x); fma2(acc[j][1], ax, wA.y);
                fma2(acc[j][2], ax, wB.x); fma2(acc[j][3], ax, wB.y);
            }
        }
    }

    float* Om = (m == 0) ? g_A1h : (m == 1) ? g_A2h : (m == 2) ? g_B1h : g_B2h;
    #pragma unroll
    for (int j = 0; j < 8; j++) {
        int node = nb0 + rb + 4 * j;
        if (node < NN) {
            float4 bia = *(const float4*)&bsm[m * 64 + c0];
            float4 bib = *(const float4*)&bsm[m * 64 + c0 + 4];
            float2 t0 = unpk(acc[j][0]), t1 = unpk(acc[j][1]);
            float2 t2 = unpk(acc[j][2]), t3 = unpk(acc[j][3]);
            float4* op = (float4*)&Om[(size_t)node * 64 + c0];
            op[0] = make_float4(t0.x + bia.x, t0.y + bia.y, t1.x + bia.z, t1.y + bia.w);
            op[1] = make_float4(t2.x + bib.x, t2.y + bib.y, t3.x + bib.z, t3.y + bib.w);
        }
    }
}

// ---------------- K2: padded-slot CSR scatter -----------------------------------
__global__ void k_scatter(const int* __restrict__ src, const int* __restrict__ dst) {
    int i = blockIdx.x * blockDim.x + threadIdx.x;
    if (i < NE) {
        int d = dst[i];
        int r = atomicAdd(&g_deg[d], 1);
        if (r < SLOT) {
            g_slot_eid[d * SLOT + r] = i;
            g_slot_src[d * SLOT + r] = src[i];
        }
    }
}

// ---------------- K3: prep W^T bf16 hi/lo ---------------------------------------
__global__ void k_prep(const float* __restrict__ B3w) {
    int i = blockIdx.x * blockDim.x + threadIdx.x;
    if (i < 4096) {
        int n = i >> 6, k = i & 63;
        float w = B3w[k * 64 + n];
        unsigned short hi, lo;
        cvt_hilo(w, hi, lo);
        g_WT_hi[i] = hi;     // [n][k]
        g_WT_lo[i] = lo;
    }
}

// ---------------- K4: edge kernel — bf16 split mma.sync GEMM + fused epilogue ---
// 128 edges/block, 256 threads (8 warps), warp-tile = 16 edges x 64 cols.
// Smem layout (bytes):
//   [0:512)       ssm        [512:1024) dsm
//   [1024:1792)   b3s|gs|bbs (3 x 64 f32)
//   [2048:20480)  A_hi  128 x 72 bf16 (pitch 144B)
//   [20480:38912) A_lo
//   [38912:48128) B_hi  64 x 72 bf16
//   [48128:57344) B_lo
//   phase2 (after MMA):
//   [2048:40960)  xsm   128 x 76 f32 (pitch 304B)   (overlaps A + head of B_hi)
//   [40960:79872) stg   128 x 76 f32                (overlaps rest of B)
#define MT 128
#define APIT 72
#define XPIT 76
#define SM_SSM 0
#define SM_DSM 512
#define SM_PAR 1024
#define SM_AHI 2048
#define SM_ALO (SM_AHI + 128 * APIT * 2)
#define SM_BHI (SM_ALO + 128 * APIT * 2)
#define SM_BLO (SM_BHI + 64 * APIT * 2)
#define SM_XSM 2048
#define SM_STG (SM_XSM + 128 * XPIT * 4)
#define SM_EDGE (SM_STG + 128 * XPIT * 4)

__global__ void __launch_bounds__(256, 2) k_edge(
    const float* __restrict__ e,
    const int* __restrict__ src, const int* __restrict__ dst,
    const float* __restrict__ B3b,
    const float* __restrict__ lng, const float* __restrict__ lnb,
    float* __restrict__ out_e)
{
    extern __shared__ char smc[];
    int tid = threadIdx.x;
    int e0 = blockIdx.x * MT;

    int* ssm = (int*)(smc + SM_SSM);
    int* dsm = (int*)(smc + SM_DSM);
    float* b3s = (float*)(smc + SM_PAR);
    float* gs  = b3s + 64;
    float* bbs = gs + 64;
    unsigned short* Ahi = (unsigned short*)(smc + SM_AHI);
    unsigned short* Alo = (unsigned short*)(smc + SM_ALO);
    unsigned short* Bhi = (unsigned short*)(smc + SM_BHI);
    unsigned short* Blo = (unsigned short*)(smc + SM_BLO);

    // ---- load W^T bf16 hi/lo into smem ----
    for (int i = tid; i < 1024; i += 256) {       // 64 n x 16 quads of 4 bf16
        int n = i >> 4, kq = (i & 15) * 4;
        *(uint2*)&Bhi[n * APIT + kq] = ((const uint2*)g_WT_hi)[i];
        *(uint2*)&Blo[n * APIT + kq] = ((const uint2*)g_WT_lo)[i];
    }
    // ---- convert e tile to bf16 hi/lo ----
    {
        int r = tid >> 1, half = tid & 1;
        int eg = e0 + r;
        bool ok = eg < NE;
        const float4* er = (const float4*)(e + (size_t)eg * 64 + 32 * half);
        #pragma unroll
        for (int q = 0; q < 8; q++) {
            float4 v = ok ? er[q] : make_float4(0.f, 0.f, 0.f, 0.f);
            unsigned short h0, h1, h2, h3, l0, l1, l2, l3;
            cvt_hilo(v.x, h0, l0); cvt_hilo(v.y, h1, l1);
            cvt_hilo(v.z, h2, l2); cvt_hilo(v.w, h3, l3);
            int c = 32 * half + 4 * q;
            *(uint2*)&Ahi[r * APIT + c] = make_uint2((uint32_t)h0 | ((uint32_t)h1 << 16),
                                                     (uint32_t)h2 | ((uint32_t)h3 << 16));
            *(uint2*)&Alo[r * APIT + c] = make_uint2((uint32_t)l0 | ((uint32_t)l1 << 16),
                                                     (uint32_t)l2 | ((uint32_t)l3 << 16));
        }
    }
    if (tid < MT) {
        int eg = e0 + tid;
        ssm[tid] = (eg < NE) ? src[eg] : 0;
        dsm[tid] = (eg < NE) ? dst[eg] : 0;
    }
    if (tid < 64) { b3s[tid] = B3b[tid]; gs[tid] = lng[tid]; bbs[tid] = lnb[tid]; }
    __syncthreads();

    // ---- MMA: 3 passes (Ahi*Bhi, Ahi*Blo, Alo*Bhi), fp32 accum ----
    int w = tid >> 5, lane = tid & 31;
    int row = lane >> 2, qk = (lane & 3) * 2;     // A row-in-tile, k offset
    int rw = 16 * w;

    float acc[8][4];
    #pragma unroll
    for (int nt = 0; nt < 8; nt++)
        #pragma unroll
        for (int c = 0; c < 4; c++) acc[nt][c] = 0.f;

    #pragma unroll
    for (int kc = 0; kc < 4; kc++) {
        int kb = kc * 16 + qk;
        uint32_t a0 = *(const uint32_t*)&Ahi[(rw + row) * APIT + kb];
        uint32_t a1 = *(const uint32_t*)&Ahi[(rw + row + 8) * APIT + kb];
        uint32_t a2 = *(const uint32_t*)&Ahi[(rw + row) * APIT + kb + 8];
        uint32_t a3 = *(const uint32_t*)&Ahi[(rw + row + 8) * APIT + kb + 8];
        #pragma unroll
        for (int nt = 0; nt < 8; nt++) {
            int n = nt * 8 + row;
            uint32_t bh0 = *(const uint32_t*)&Bhi[n * APIT + kb];
            uint32_t bh1 = *(const uint32_t*)&Bhi[n * APIT + kb + 8];
            mma16816(acc[nt], a0, a1, a2, a3, bh0, bh1);
            uint32_t bl0 = *(const uint32_t*)&Blo[n * APIT + kb];
            uint32_t bl1 = *(const uint32_t*)&Blo[n * APIT + kb + 8];
            mma16816(acc[nt], a0, a1, a2, a3, bl0, bl1);
        }
        uint32_t c0 = *(const uint32_t*)&Alo[(rw + row) * APIT + kb];
        uint32_t c1 = *(const uint32_t*)&Alo[(rw + row + 8) * APIT + kb];
        uint32_t c2 = *(const uint32_t*)&Alo[(rw + row) * APIT + kb + 8];
        uint32_t c3 = *(const uint32_t*)&Alo[(rw + row + 8) * APIT + kb + 8];
        #pragma unroll
        for (int nt = 0; nt < 8; nt++) {
            int n = nt * 8 + row;
            uint32_t bh0 = *(const uint32_t*)&Bhi[n * APIT + kb];
            uint32_t bh1 = *(const uint32_t*)&Bhi[n * APIT + kb + 8];
            mma16816(acc[nt], c0, c1, c2, c3, bh0, bh1);
        }
    }
    __syncthreads();          // A/B smem dead

    // ---- write C to xsm; stage B1h[src]+B2h[dst] into stg ----
    float* xsm = (float*)(smc + SM_XSM);
    float* stg = (float*)(smc + SM_STG);
    {
        int col = 2 * (lane & 3);
        #pragma unroll
        for (int nt = 0; nt < 8; nt++) {
            int c = nt * 8 + col;
            *(float2*)&xsm[(rw + row) * XPIT + c]     = make_float2(acc[nt][0], acc[nt][1]);
            *(float2*)&xsm[(rw + row + 8) * XPIT + c] = make_float2(acc[nt][2], acc[nt][3]);
        }
    }
    for (int i = tid; i < MT * 16; i += 256) {
        int r = i >> 4, p = i & 15;
        int s = ssm[r], d = dsm[r];
        float4 u = ((const float4*)(g_B1h + (size_t)s * 64))[p];
        float4 v = ((const float4*)(g_B2h + (size_t)d * 64))[p];
        *(float4*)&stg[r * XPIT + 4 * p] = make_float4(u.x + v.x, u.y + v.y, u.z + v.z, u.w + v.w);
    }
    __syncthreads();

    // ---- thread-per-row LN epilogue ----
    if (tid < MT) {
        int r = tid;
        float x[64];
        float sA = 0.f, sQ = 0.f;
        #pragma unroll
        for (int p = 0; p < 16; p++) {
            float4 xv = *(float4*)&xsm[r * XPIT + 4 * p];
            float4 uv = *(float4*)&stg[r * XPIT + 4 * p];
            float4 bv = *(const float4*)&b3s[4 * p];
            x[4 * p + 0] = xv.x + uv.x + bv.x;
            x[4 * p + 1] = xv.y + uv.y + bv.y;
            x[4 * p + 2] = xv.z + uv.z + bv.z;
            x[4 * p + 3] = xv.w + uv.w + bv.w;
            sA += x[4 * p + 0] + x[4 * p + 1] + x[4 * p + 2] + x[4 * p + 3];
            sQ += x[4 * p + 0] * x[4 * p + 0] + x[4 * p + 1] * x[4 * p + 1]
                + x[4 * p + 2] * x[4 * p + 2] + x[4 * p + 3] * x[4 * p + 3];
        }
        float mu = sA * 0.015625f;
        float var = sQ * 0.015625f - mu * mu;
        float rstd = rsqrtf(var + 1e-5f);
        #pragma unroll
        for (int p = 0; p < 16; p++) {
            float4 gv = *(const float4*)&gs[4 * p];
            float4 bv = *(const float4*)&bbs[4 * p];
            float4 o;
            o.x = fmaxf((x[4 * p + 0] - mu) * rstd * gv.x + bv.x, 0.f);
            o.y = fmaxf((x[4 * p + 1] - mu) * rstd * gv.y + bv.y, 0.f);
            o.z = fmaxf((x[4 * p + 2] - mu) * rstd * gv.z + bv.z, 0.f);
            o.w = fmaxf((x[4 * p + 3] - mu) * rstd * gv.w + bv.w, 0.f);
            *(float4*)&xsm[r * XPIT + 4 * p] = o;
        }
    }
    __syncthreads();

    // ---- coalesced store: out_e = relu(LN(..)) + e ----
    for (int i = tid; i < MT * 16; i += 256) {
        int r = i >> 4, p = i & 15;
        int eg = e0 + r;
        if (eg < NE) {
            float4 ev = ((const float4*)(e + (size_t)eg * 64))[p];
            float4 o = *(float4*)&xsm[r * XPIT + 4 * p];
            ((float4*)(out_e + (size_t)eg * 64))[p] =
                make_float4(o.x + ev.x, o.y + ev.y, o.z + ev.z, o.w + ev.w);
        }
    }
}

// ---------------- K5: gather-side aggregation + node LN/out ---------------------
__global__ void __launch_bounds__(256) k_node(
    const float* __restrict__ h,
    const float* __restrict__ lng, const float* __restrict__ lnb,
    const float* __restrict__ out_e, float* __restrict__ out_h)
{
    int wid = threadIdx.x >> 5, lane = threadIdx.x & 31;
    int n = blockIdx.x * 8 + wid;
    if (n >= NN) return;

    int deg = g_deg[n];
    if (deg > SLOT) deg = SLOT;
    const int* eids = &g_slot_eid[(size_t)n * SLOT];
    const int* srcs = &g_slot_src[(size_t)n * SLOT];

    int kmax = deg < 32 ? deg : 32;
    int eidr = 0, sr = 0;
    if (lane < kmax) { eidr = eids[lane]; sr = srcs[lane]; }

    float2 ah = make_float2(0.f, 0.f), as = make_float2(0.f, 0.f);

    float2 ej_c, a2_c;
    if (kmax > 0) {
        int eid0 = __shfl_sync(0xffffffffu, eidr, 0);
        int s0   = __shfl_sync(0xffffffffu, sr, 0);
        ej_c = *(const float2*)&out_e[(size_t)eid0 * 64 + 2 * lane];
        a2_c = *(const float2*)&g_A2h[(size_t)s0 * 64 + 2 * lane];
    }
    for (int k = 0; k < kmax; k++) {
        float2 ej = ej_c, a2 = a2_c;
        if (k + 1 < kmax) {
            int eidn = __shfl_sync(0xffffffffu, eidr, k + 1);
            int sn   = __shfl_sync(0xffffffffu, sr, k + 1);
            ej_c = *(const float2*)&out_e[(size_t)eidn * 64 + 2 * lane];
            a2_c = *(const float2*)&g_A2h[(size_t)sn * 64 + 2 * lane];
        }
        float2 sg;
        sg.x = __fdividef(1.f, 1.f + __expf(-ej.x));
        sg.y = __fdividef(1.f, 1.f + __expf(-ej.y));
        ah.x += a2.x * sg.x; ah.y += a2.y * sg.y;
        as.x += sg.x;        as.y += sg.y;
    }
    for (int k = 32; k < deg; k++) {
        int eid = eids[k];
        int s   = srcs[k];
        float2 ej = *(const float2*)&out_e[(size_t)eid * 64 + 2 * lane];
        float2 a2 = *(const float2*)&g_A2h[(size_t)s * 64 + 2 * lane];
        float2 sg;
        sg.x = __fdividef(1.f, 1.f + __expf(-ej.x));
        sg.y = __fdividef(1.f, 1.f + __expf(-ej.y));
        ah.x += a2.x * sg.x; ah.y += a2.y * sg.y;
        as.x += sg.x;        as.y += sg.y;
    }

    float2 a1 = *(const float2*)&g_A1h[(size_t)n * 64 + 2 * lane];
    float2 x;
    x.x = a1.x + ah.x / (as.x + 1e-6f);
    x.y = a1.y + ah.y / (as.y + 1e-6f);

    float sA = x.x + x.y, sQ = x.x * x.x + x.y * x.y;
    #pragma unroll
    for (int off = 16; off; off >>= 1) {
        sA += __shfl_xor_sync(0xffffffffu, sA, off);
        sQ += __shfl_xor_sync(0xffffffffu, sQ, off);
    }
    float mu = sA * 0.015625f;
    float var = sQ * 0.015625f - mu * mu;
    float rstd = rsqrtf(var + 1e-5f);

    float2 g2 = *(const float2*)&lng[2 * lane];
    float2 b2 = *(const float2*)&lnb[2 * lane];
    float2 hr = *(const float2*)&h[(size_t)n * 64 + 2 * lane];
    float2 outv;
    outv.x = fmaxf((x.x - mu) * rstd * g2.x + b2.x, 0.f) + hr.x;
    outv.y = fmaxf((x.y - mu) * rstd * g2.y + b2.y, 0.f) + hr.y;
    *(float2*)&out_h[(size_t)n * 64 + 2 * lane] = outv;
}

// ---------------- launch ----------------
extern "C" void kernel_launch(void* const* d_in, const int* in_sizes, int n_in,
                              void* d_out, int out_size)
{
    const float* h   = (const float*)d_in[0];
    const float* e   = (const float*)d_in[1];
    const int*   src = (const int*)d_in[2];
    const int*   dst = (const int*)d_in[3];
    const float* A1w = (const float*)d_in[4];
    const float* A1b = (const float*)d_in[5];
    const float* A2w = (const float*)d_in[6];
    const float* A2b = (const float*)d_in[7];
    const float* B1w = (const float*)d_in[8];
    const float* B1b = (const float*)d_in[9];
    const float* B2w = (const float*)d_in[10];
    const float* B2b = (const float*)d_in[11];
    const float* B3w = (const float*)d_in[12];
    const float* B3b = (const float*)d_in[13];
    const float* lneg = (const float*)d_in[14];
    const float* lneb = (const float*)d_in[15];
    const float* lnhg = (const float*)d_in[16];
    const float* lnhb = (const float*)d_in[17];

    float* out_h = (float*)d_out;
    float* out_e = out_h + (size_t)NN * 64;

    cudaFuncSetAttribute(k_proj, cudaFuncAttributeMaxDynamicSharedMemorySize, PROJ_SMEM);
    cudaFuncSetAttribute(k_edge, cudaFuncAttributeMaxDynamicSharedMemorySize, SM_EDGE);

    k_proj<<<(NN + 63) / 64, 256, PROJ_SMEM>>>(h, A1w, A1b, A2w, A2b, B1w, B1b, B2w, B2b);
    k_scatter<<<(NE + 255) / 256, 256>>>(src, dst);
    k_prep<<<16, 256>>>(B3w);
    k_edge<<<(NE + MT - 1) / MT, 256, SM_EDGE>>>(e, src, dst, B3b, lneg, lneb, out_e);
    k_node<<<(NN + 7) / 8, 256>>>(h, lnhg, lnhb, out_e, out_h);
}

// round 7
// speedup vs baseline: 1.1311x; 1.1311x over previous
#include <cuda_runtime.h>
#include <cuda_bf16.h>
#include <cstdint>

#define NN 100000
#define NE 1000000
#define SLOT 128
#define EP 68          // smem row pitch (floats) for h tiles in k_proj
#define WP 72          // W smem row pitch with half-row shift (k_proj)

// ---------------- scratch (static device globals; no allocation) ----------------
__device__ float g_A1h[NN * 64];
__device__ float g_A2h[NN * 64];
__device__ float g_B1h[NN * 64];
__device__ float g_B2h[NN * 64];
__device__ int g_deg[NN];
__device__ int g_slot_eid[NN * SLOT];
__device__ int g_slot_src[NN * SLOT];
__device__ __align__(16) unsigned short g_WT_hi[64 * 64];   // B3w^T bf16 hi  [n][k]
__device__ __align__(16) unsigned short g_WT_lo[64 * 64];   // B3w^T bf16 lo  [n][k]

typedef unsigned long long ull;

static __device__ __forceinline__ ull splat2(float x) {
    ull r; asm("mov.b64 %0, {%1, %1};" : "=l"(r) : "f"(x)); return r;
}
static __device__ __forceinline__ void fma2(ull &c, ull a, ull b) {
    asm("fma.rn.f32x2 %0, %1, %2, %3;" : "=l"(c) : "l"(a), "l"(b), "l"(c));
}
static __device__ __forceinline__ float2 unpk(ull v) {
    float2 f; asm("mov.b64 {%0, %1}, %2;" : "=f"(f.x), "=f"(f.y) : "l"(v)); return f;
}
static __device__ __forceinline__ int wofs(int k, int c4) {
    return k * WP + c4 + ((c4 & 32) >> 3);
}
static __device__ __forceinline__ void cvt_hilo(float x, unsigned short &hi, unsigned short &lo) {
    __nv_bfloat16 h = __float2bfloat16(x);
    float r = x - __bfloat162float(h);
    __nv_bfloat16 l = __float2bfloat16(r);
    hi = *reinterpret_cast<unsigned short*>(&h);
    lo = *reinterpret_cast<unsigned short*>(&l);
}
static __device__ __forceinline__ void mma16816(float* c, uint32_t a0, uint32_t a1,
                                                uint32_t a2, uint32_t a3,
                                                uint32_t b0, uint32_t b1) {
    asm volatile(
        "mma.sync.aligned.m16n8k16.row.col.f32.bf16.bf16.f32 "
        "{%0,%1,%2,%3}, {%4,%5,%6,%7}, {%8,%9}, {%0,%1,%2,%3};"
        : "+f"(c[0]), "+f"(c[1]), "+f"(c[2]), "+f"(c[3])
        : "r"(a0), "r"(a1), "r"(a2), "r"(a3), "r"(b0), "r"(b1));
}

// ---------------- K1: node projections (fp32 FFMA2 path) ------------------------
#define PROJ_SMEM ((4 * 64 * WP + 64 * EP + 256) * 4)

__global__ void __launch_bounds__(256, 2) k_proj(
    const float* __restrict__ h,
    const float* __restrict__ A1w, const float* __restrict__ A1b,
    const float* __restrict__ A2w, const float* __restrict__ A2b,
    const float* __restrict__ B1w, const float* __restrict__ B1b,
    const float* __restrict__ B2w, const float* __restrict__ B2b)
{
    extern __shared__ float sm[];
    float* Wsm = sm;
    float* hsm = sm + 4 * 64 * WP;
    float* bsm = hsm + 64 * EP;

    int tid = threadIdx.x;
    int nb0 = blockIdx.x * 64;

    const float* Ws[4] = {A1w, A2w, B1w, B2w};
    #pragma unroll
    for (int m = 0; m < 4; m++) {
        float* Wm = Wsm + m * 64 * WP;
        for (int i = tid; i < 1024; i += 256) {
            int k = i >> 4, c4 = 4 * (i & 15);
            *(float4*)&Wm[wofs(k, c4)] = ((const float4*)Ws[m])[i];
        }
    }
    {
        const float* Bs[4] = {A1b, A2b, B1b, B2b};
        bsm[tid] = Bs[tid >> 6][tid & 63];
    }
    for (int i = tid; i < 64 * 16; i += 256) {
        int r = i >> 4, p = i & 15;
        int node = nb0 + r;
        float4 v = make_float4(0.f, 0.f, 0.f, 0.f);
        if (node < NN) v = ((const float4*)h)[node * 16 + p];
        *(float4*)&hsm[r * EP + 4 * p] = v;
    }
    if (tid < 64 && nb0 + tid < NN) g_deg[nb0 + tid] = 0;
    __syncthreads();

    int m = tid >> 6;
    int wloc = (tid >> 5) & 1;
    int lane = tid & 31;
    int g = lane >> 3, cg = lane & 7;
    int c0 = 8 * cg;
    int c0s = c0 + ((c0 & 32) >> 3);
    int rb = 32 * wloc + g;
    const float* Wm = Wsm + m * 64 * WP;

    ull acc[8][4];
    #pragma unroll
    for (int j = 0; j < 8; j++)
        #pragma unroll
        for (int c = 0; c < 4; c++) acc[j][c] = 0ull;

    #pragma unroll 2
    for (int k4 = 0; k4 < 16; k4++) {
        float4 a[8];
        #pragma unroll
        for (int j = 0; j < 8; j++)
            a[j] = *(const float4*)&hsm[(rb + 4 * j) * EP + 4 * k4];
        #pragma unroll
        for (int kk = 0; kk < 4; kk++) {
            const float* wr = &Wm[(4 * k4 + kk) * WP];
            ulonglong2 wA = *(const ulonglong2*)&wr[c0s];
            ulonglong2 wB = *(const ulonglong2*)&wr[c0s + 4];
            #pragma unroll
            for (int j = 0; j < 8; j++) {
                float av = (kk == 0) ? a[j].x : (kk == 1) ? a[j].y : (kk == 2) ? a[j].z : a[j].w;
                ull ax = splat2(av);
                fma2(acc[j][0], ax, wA.x); fma2(acc[j][1], ax, wA.y);
                fma2(acc[j][2], ax, wB.x); fma2(acc[j][3], ax, wB.y);
            }
        }
    }

    float* Om = (m == 0) ? g_A1h : (m == 1) ? g_A2h : (m == 2) ? g_B1h : g_B2h;
    #pragma unroll
    for (int j = 0; j < 8; j++) {
        int node = nb0 + rb + 4 * j;
        if (node < NN) {
            float4 bia = *(const float4*)&bsm[m * 64 + c0];
            float4 bib = *(const float4*)&bsm[m * 64 + c0 + 4];
            float2 t0 = unpk(acc[j][0]), t1 = unpk(acc[j][1]);
            float2 t2 = unpk(acc[j][2]), t3 = unpk(acc[j][3]);
            float4* op = (float4*)&Om[(size_t)node * 64 + c0];
            op[0] = make_float4(t0.x + bia.x, t0.y + bia.y, t1.x + bia.z, t1.y + bia.w);
            op[1] = make_float4(t2.x + bib.x, t2.y + bib.y, t3.x + bib.z, t3.y + bib.w);
        }
    }
}

// ---------------- K2: padded-slot CSR scatter -----------------------------------
__global__ void k_scatter(const int* __restrict__ src, const int* __restrict__ dst) {
    int i = blockIdx.x * blockDim.x + threadIdx.x;
    if (i < NE) {
        int d = dst[i];
        int r = atomicAdd(&g_deg[d], 1);
        if (r < SLOT) {
            g_slot_eid[d * SLOT + r] = i;
            g_slot_src[d * SLOT + r] = src[i];
        }
    }
}

// ---------------- K3: prep W^T bf16 hi/lo ---------------------------------------
__global__ void k_prep(const float* __restrict__ B3w) {
    int i = blockIdx.x * blockDim.x + threadIdx.x;
    if (i < 4096) {
        int n = i >> 6, k = i & 63;
        float w = B3w[k * 64 + n];
        unsigned short hi, lo;
        cvt_hilo(w, hi, lo);
        g_WT_hi[i] = hi;     // [n][k]
        g_WT_lo[i] = lo;
    }
}

// ---------------- K4: edge kernel — bf16 split mma.sync GEMM + fused epilogue ---
// 128 edges/block, 256 threads (8 warps), warp-tile = 16 edges x 64 cols.
// Smem (57344 B total → 3 blocks/SM):
//   [0:512) ssm  [512:1024) dsm  [1024:1792) b3s|gs|bbs
//   [2048:20480)  A_hi 128 x 72 bf16      [20480:38912) A_lo
//   [38912:48128) B_hi  64 x 72 bf16      [48128:57344) B_lo
//   phase2: xsm = [2048:38912) 128 x 72 f32 (overlaps A exactly)
#define MT 128
#define APIT 72
#define XPIT 72
#define SM_SSM 0
#define SM_DSM 512
#define SM_PAR 1024
#define SM_AHI 2048
#define SM_ALO (SM_AHI + 128 * APIT * 2)
#define SM_BHI (SM_ALO + 128 * APIT * 2)
#define SM_BLO (SM_BHI + 64 * APIT * 2)
#define SM_EDGE (SM_BLO + 64 * APIT * 2)

__global__ void __launch_bounds__(256, 3) k_edge(
    const float* __restrict__ e,
    const int* __restrict__ src, const int* __restrict__ dst,
    const float* __restrict__ B3b,
    const float* __restrict__ lng, const float* __restrict__ lnb,
    float* __restrict__ out_e)
{
    extern __shared__ char smc[];
    int tid = threadIdx.x;
    int e0 = blockIdx.x * MT;

    int* ssm = (int*)(smc + SM_SSM);
    int* dsm = (int*)(smc + SM_DSM);
    float* b3s = (float*)(smc + SM_PAR);
    float* gs  = b3s + 64;
    float* bbs = gs + 64;
    unsigned short* Ahi = (unsigned short*)(smc + SM_AHI);
    unsigned short* Alo = (unsigned short*)(smc + SM_ALO);
    unsigned short* Bhi = (unsigned short*)(smc + SM_BHI);
    unsigned short* Blo = (unsigned short*)(smc + SM_BLO);

    // ---- W^T bf16 hi/lo into smem ----
    for (int i = tid; i < 1024; i += 256) {
        int n = i >> 4, kq = (i & 15) * 4;
        *(uint2*)&Bhi[n * APIT + kq] = ((const uint2*)g_WT_hi)[i];
        *(uint2*)&Blo[n * APIT + kq] = ((const uint2*)g_WT_lo)[i];
    }
    // ---- convert e tile to bf16 hi/lo (coalesced, 16 threads/row) ----
    for (int i = tid; i < MT * 16; i += 256) {
        int r = i >> 4, p = i & 15;
        int eg = e0 + r;
        float4 v = (eg < NE) ? ((const float4*)e)[(size_t)eg * 16 + p]
                             : make_float4(0.f, 0.f, 0.f, 0.f);
        unsigned short h0, h1, h2, h3, l0, l1, l2, l3;
        cvt_hilo(v.x, h0, l0); cvt_hilo(v.y, h1, l1);
        cvt_hilo(v.z, h2, l2); cvt_hilo(v.w, h3, l3);
        *(uint2*)&Ahi[r * APIT + 4 * p] = make_uint2((uint32_t)h0 | ((uint32_t)h1 << 16),
                                                     (uint32_t)h2 | ((uint32_t)h3 << 16));
        *(uint2*)&Alo[r * APIT + 4 * p] = make_uint2((uint32_t)l0 | ((uint32_t)l1 << 16),
                                                     (uint32_t)l2 | ((uint32_t)l3 << 16));
    }
    if (tid < MT) {
        int eg = e0 + tid;
        ssm[tid] = (eg < NE) ? src[eg] : 0;
        dsm[tid] = (eg < NE) ? dst[eg] : 0;
    }
    if (tid < 64) { b3s[tid] = B3b[tid]; gs[tid] = lng[tid]; bbs[tid] = lnb[tid]; }
    __syncthreads();

    // ---- MMA: 3 passes (Ahi*Bhi, Ahi*Blo, Alo*Bhi), fp32 accum ----
    int w = tid >> 5, lane = tid & 31;
    int row = lane >> 2, qk = (lane & 3) * 2;
    int rw = 16 * w;

    float acc[8][4];
    #pragma unroll
    for (int nt = 0; nt < 8; nt++)
        #pragma unroll
        for (int c = 0; c < 4; c++) acc[nt][c] = 0.f;

    #pragma unroll
    for (int kc = 0; kc < 4; kc++) {
        int kb = kc * 16 + qk;
        uint32_t a0 = *(const uint32_t*)&Ahi[(rw + row) * APIT + kb];
        uint32_t a1 = *(const uint32_t*)&Ahi[(rw + row + 8) * APIT + kb];
        uint32_t a2 = *(const uint32_t*)&Ahi[(rw + row) * APIT + kb + 8];
        uint32_t a3 = *(const uint32_t*)&Ahi[(rw + row + 8) * APIT + kb + 8];
        #pragma unroll
        for (int nt = 0; nt < 8; nt++) {
            int n = nt * 8 + row;
            uint32_t bh0 = *(const uint32_t*)&Bhi[n * APIT + kb];
            uint32_t bh1 = *(const uint32_t*)&Bhi[n * APIT + kb + 8];
            mma16816(acc[nt], a0, a1, a2, a3, bh0, bh1);
            uint32_t bl0 = *(const uint32_t*)&Blo[n * APIT + kb];
            uint32_t bl1 = *(const uint32_t*)&Blo[n * APIT + kb + 8];
            mma16816(acc[nt], a0, a1, a2, a3, bl0, bl1);
        }
        uint32_t c0 = *(const uint32_t*)&Alo[(rw + row) * APIT + kb];
        uint32_t c1 = *(const uint32_t*)&Alo[(rw + row + 8) * APIT + kb];
        uint32_t c2 = *(const uint32_t*)&Alo[(rw + row) * APIT + kb + 8];
        uint32_t c3 = *(const uint32_t*)&Alo[(rw + row + 8) * APIT + kb + 8];
        #pragma unroll
        for (int nt = 0; nt < 8; nt++) {
            int n = nt * 8 + row;
            uint32_t bh0 = *(const uint32_t*)&Bhi[n * APIT + kb];
            uint32_t bh1 = *(const uint32_t*)&Bhi[n * APIT + kb + 8];
            mma16816(acc[nt], c0, c1, c2, c3, bh0, bh1);
        }
    }
    __syncthreads();          // A smem dead → xsm

    float* xsm = (float*)(smc + SM_AHI);
    // ---- write C fragments to xsm ----
    {
        int col = 2 * (lane & 3);
        #pragma unroll
        for (int nt = 0; nt < 8; nt++) {
            int c = nt * 8 + col;
            *(float2*)&xsm[(rw + row) * XPIT + c]     = make_float2(acc[nt][0], acc[nt][1]);
            *(float2*)&xsm[(rw + row + 8) * XPIT + c] = make_float2(acc[nt][2], acc[nt][3]);
        }
    }
    __syncthreads();
    // ---- gather-add: xsm += B1h[src] + B2h[dst] + b3 (coalesced) ----
    for (int i = tid; i < MT * 16; i += 256) {
        int r = i >> 4, p = i & 15;
        int s = ssm[r], d = dsm[r];
        float4 u = ((const float4*)(g_B1h + (size_t)s * 64))[p];
        float4 v = ((const float4*)(g_B2h + (size_t)d * 64))[p];
        float4 b = *(const float4*)&b3s[4 * p];
        float4 xv = *(float4*)&xsm[r * XPIT + 4 * p];
        xv.x += u.x + v.x + b.x; xv.y += u.y + v.y + b.y;
        xv.z += u.z + v.z + b.z; xv.w += u.w + v.w + b.w;
        *(float4*)&xsm[r * XPIT + 4 * p] = xv;
    }
    __syncthreads();

    // ---- LN: 2 threads/row, interleaved quads, shfl combine ----
    {
        int r = tid >> 1, half = tid & 1;
        float x[32];
        float sA = 0.f, sQ = 0.f;
        #pragma unroll
        for (int p = 0; p < 8; p++) {
            int c = p * 8 + half * 4;
            float4 xv = *(float4*)&xsm[r * XPIT + c];
            x[4 * p + 0] = xv.x; x[4 * p + 1] = xv.y;
            x[4 * p + 2] = xv.z; x[4 * p + 3] = xv.w;
            sA += xv.x + xv.y + xv.z + xv.w;
            sQ += xv.x * xv.x + xv.y * xv.y + xv.z * xv.z + xv.w * xv.w;
        }
        sA += __shfl_xor_sync(0xffffffffu, sA, 1);
        sQ += __shfl_xor_sync(0xffffffffu, sQ, 1);
        float mu = sA * 0.015625f;
        float var = sQ * 0.015625f - mu * mu;
        float rstd = rsqrtf(var + 1e-5f);
        #pragma unroll
        for (int p = 0; p < 8; p++) {
            int c = p * 8 + half * 4;
            float4 gv = *(const float4*)&gs[c];
            float4 bv = *(const float4*)&bbs[c];
            float4 o;
            o.x = fmaxf((x[4 * p + 0] - mu) * rstd * gv.x + bv.x, 0.f);
            o.y = fmaxf((x[4 * p + 1] - mu) * rstd * gv.y + bv.y, 0.f);
            o.z = fmaxf((x[4 * p + 2] - mu) * rstd * gv.z + bv.z, 0.f);
            o.w = fmaxf((x[4 * p + 3] - mu) * rstd * gv.w + bv.w, 0.f);
            *(float4*)&xsm[r * XPIT + c] = o;
        }
    }
    __syncthreads();

    // ---- coalesced store: out_e = relu(LN(..)) + e ----
    for (int i = tid; i < MT * 16; i += 256) {
        int r = i >> 4, p = i & 15;
        int eg = e0 + r;
        if (eg < NE) {
            float4 ev = ((const float4*)e)[(size_t)eg * 16 + p];
            float4 o = *(float4*)&xsm[r * XPIT + 4 * p];
            ((float4*)(out_e + (size_t)eg * 64))[p] =
                make_float4(o.x + ev.x, o.y + ev.y, o.z + ev.z, o.w + ev.w);
        }
    }
}

// ---------------- K5: gather-side aggregation + node LN/out ---------------------
__global__ void __launch_bounds__(256) k_node(
    const float* __restrict__ h,
    const float* __restrict__ lng, const float* __restrict__ lnb,
    const float* __restrict__ out_e, float* __restrict__ out_h)
{
    int wid = threadIdx.x >> 5, lane = threadIdx.x & 31;
    int n = blockIdx.x * 8 + wid;
    if (n >= NN) return;

    int deg = g_deg[n];
    if (deg > SLOT) deg = SLOT;
    const int* eids = &g_slot_eid[(size_t)n * SLOT];
    const int* srcs = &g_slot_src[(size_t)n * SLOT];

    int kmax = deg < 32 ? deg : 32;
    int eidr = 0, sr = 0;
    if (lane < kmax) { eidr = eids[lane]; sr = srcs[lane]; }

    float2 ah = make_float2(0.f, 0.f), as = make_float2(0.f, 0.f);

    float2 ej_c, a2_c;
    if (kmax > 0) {
        int eid0 = __shfl_sync(0xffffffffu, eidr, 0);
        int s0   = __shfl_sync(0xffffffffu, sr, 0);
        ej_c = *(const float2*)&out_e[(size_t)eid0 * 64 + 2 * lane];
        a2_c = *(const float2*)&g_A2h[(size_t)s0 * 64 + 2 * lane];
    }
    for (int k = 0; k < kmax; k++) {
        float2 ej = ej_c, a2 = a2_c;
        if (k + 1 < kmax) {
            int eidn = __shfl_sync(0xffffffffu, eidr, k + 1);
            int sn   = __shfl_sync(0xffffffffu, sr, k + 1);
            ej_c = *(const float2*)&out_e[(size_t)eidn * 64 + 2 * lane];
            a2_c = *(const float2*)&g_A2h[(size_t)sn * 64 + 2 * lane];
        }
        float2 sg;
        sg.x = __fdividef(1.f, 1.f + __expf(-ej.x));
        sg.y = __fdividef(1.f, 1.f + __expf(-ej.y));
        ah.x += a2.x * sg.x; ah.y += a2.y * sg.y;
        as.x += sg.x;        as.y += sg.y;
    }
    for (int k = 32; k < deg; k++) {
        int eid = eids[k];
        int s   = srcs[k];
        float2 ej = *(const float2*)&out_e[(size_t)eid * 64 + 2 * lane];
        float2 a2 = *(const float2*)&g_A2h[(size_t)s * 64 + 2 * lane];
        float2 sg;
        sg.x = __fdividef(1.f, 1.f + __expf(-ej.x));
        sg.y = __fdividef(1.f, 1.f + __expf(-ej.y));
        ah.x += a2.x * sg.x; ah.y += a2.y * sg.y;
        as.x += sg.x;        as.y += sg.y;
    }

    float2 a1 = *(const float2*)&g_A1h[(size_t)n * 64 + 2 * lane];
    float2 x;
    x.x = a1.x + ah.x / (as.x + 1e-6f);
    x.y = a1.y + ah.y / (as.y + 1e-6f);

    float sA = x.x + x.y, sQ = x.x * x.x + x.y * x.y;
    #pragma unroll
    for (int off = 16; off; off >>= 1) {
        sA += __shfl_xor_sync(0xffffffffu, sA, off);
        sQ += __shfl_xor_sync(0xffffffffu, sQ, off);
    }
    float mu = sA * 0.015625f;
    float var = sQ * 0.015625f - mu * mu;
    float rstd = rsqrtf(var + 1e-5f);

    float2 g2 = *(const float2*)&lng[2 * lane];
    float2 b2 = *(const float2*)&lnb[2 * lane];
    float2 hr = *(const float2*)&h[(size_t)n * 64 + 2 * lane];
    float2 outv;
    outv.x = fmaxf((x.x - mu) * rstd * g2.x + b2.x, 0.f) + hr.x;
    outv.y = fmaxf((x.y - mu) * rstd * g2.y + b2.y, 0.f) + hr.y;
    *(float2*)&out_h[(size_t)n * 64 + 2 * lane] = outv;
}

// ---------------- launch ----------------
extern "C" void kernel_launch(void* const* d_in, const int* in_sizes, int n_in,
                              void* d_out, int out_size)
{
    const float* h   = (const float*)d_in[0];
    const float* e   = (const float*)d_in[1];
    const int*   src = (const int*)d_in[2];
    const int*   dst = (const int*)d_in[3];
    const float* A1w = (const float*)d_in[4];
    const float* A1b = (const float*)d_in[5];
    const float* A2w = (const float*)d_in[6];
    const float* A2b = (const float*)d_in[7];
    const float* B1w = (const float*)d_in[8];
    const float* B1b = (const float*)d_in[9];
    const float* B2w = (const float*)d_in[10];
    const float* B2b = (const float*)d_in[11];
    const float* B3w = (const float*)d_in[12];
    const float* B3b = (const float*)d_in[13];
    const float* lneg = (const float*)d_in[14];
    const float* lneb = (const float*)d_in[15];
    const float* lnhg = (const float*)d_in[16];
    const float* lnhb = (const float*)d_in[17];

    float* out_h = (float*)d_out;
    float* out_e = out_h + (size_t)NN * 64;

    cudaFuncSetAttribute(k_proj, cudaFuncAttributeMaxDynamicSharedMemorySize, PROJ_SMEM);
    cudaFuncSetAttribute(k_edge, cudaFuncAttributeMaxDynamicSharedMemorySize, SM_EDGE);

    k_proj<<<(NN + 63) / 64, 256, PROJ_SMEM>>>(h, A1w, A1b, A2w, A2b, B1w, B1b, B2w, B2b);
    k_scatter<<<(NE + 255) / 256, 256>>>(src, dst);
    k_prep<<<16, 256>>>(B3w);
    k_edge<<<(NE + MT - 1) / MT, 256, SM_EDGE>>>(e, src, dst, B3b, lneg, lneb, out_e);
    k_node<<<(NN + 7) / 8, 256>>>(h, lnhg, lnhb, out_e, out_h);
}

// round 8
// speedup vs baseline: 1.2128x; 1.0722x over previous
#include <cuda_runtime.h>
#include <cuda_bf16.h>
#include <cstdint>

#define NN 100000
#define NE 1000000
#define SLOT 128
#define EP 68          // smem row pitch (floats) for h tiles in k_proj
#define WP 72          // W smem row pitch with half-row shift (k_proj)

// ---------------- scratch (static device globals; no allocation) ----------------
__device__ float g_A1h[NN * 64];
__device__ float g_A2h[NN * 64];
__device__ float g_B1h[NN * 64];
__device__ float g_B2h[NN * 64];
__device__ int g_deg[NN];
__device__ int2 g_slot[NN * SLOT];                          // (eid, src)
__device__ __align__(16) unsigned short g_WT_hi[64 * 64];   // B3w^T bf16 hi  [n][k]
__device__ __align__(16) unsigned short g_WT_lo[64 * 64];   // B3w^T bf16 lo  [n][k]

typedef unsigned long long ull;

static __device__ __forceinline__ ull splat2(float x) {
    ull r; asm("mov.b64 %0, {%1, %1};" : "=l"(r) : "f"(x)); return r;
}
static __device__ __forceinline__ void fma2(ull &c, ull a, ull b) {
    asm("fma.rn.f32x2 %0, %1, %2, %3;" : "=l"(c) : "l"(a), "l"(b), "l"(c));
}
static __device__ __forceinline__ float2 unpk(ull v) {
    float2 f; asm("mov.b64 {%0, %1}, %2;" : "=f"(f.x), "=f"(f.y) : "l"(v)); return f;
}
static __device__ __forceinline__ int wofs(int k, int c4) {
    return k * WP + c4 + ((c4 & 32) >> 3);
}
static __device__ __forceinline__ void cvt_hilo(float x, unsigned short &hi, unsigned short &lo) {
    __nv_bfloat16 h = __float2bfloat16(x);
    float r = x - __bfloat162float(h);
    __nv_bfloat16 l = __float2bfloat16(r);
    hi = *reinterpret_cast<unsigned short*>(&h);
    lo = *reinterpret_cast<unsigned short*>(&l);
}
// float2 -> packed bf16x2 hi and lo
static __device__ __forceinline__ void f2_hilo(float2 v, uint32_t &hi, uint32_t &lo) {
    unsigned short h0, l0, h1, l1;
    cvt_hilo(v.x, h0, l0); cvt_hilo(v.y, h1, l1);
    hi = (uint32_t)h0 | ((uint32_t)h1 << 16);
    lo = (uint32_t)l0 | ((uint32_t)l1 << 16);
}
static __device__ __forceinline__ void mma16816(float* c, uint32_t a0, uint32_t a1,
                                                uint32_t a2, uint32_t a3,
                                                uint32_t b0, uint32_t b1) {
    asm volatile(
        "mma.sync.aligned.m16n8k16.row.col.f32.bf16.bf16.f32 "
        "{%0,%1,%2,%3}, {%4,%5,%6,%7}, {%8,%9}, {%0,%1,%2,%3};"
        : "+f"(c[0]), "+f"(c[1]), "+f"(c[2]), "+f"(c[3])
        : "r"(a0), "r"(a1), "r"(a2), "r"(a3), "r"(b0), "r"(b1));
}

// ---------------- K1: node projections (fp32 FFMA2 path) ------------------------
#define PROJ_SMEM ((4 * 64 * WP + 64 * EP + 256) * 4)

__global__ void __launch_bounds__(256, 2) k_proj(
    const float* __restrict__ h,
    const float* __restrict__ A1w, const float* __restrict__ A1b,
    const float* __restrict__ A2w, const float* __restrict__ A2b,
    const float* __restrict__ B1w, const float* __restrict__ B1b,
    const float* __restrict__ B2w, const float* __restrict__ B2b)
{
    extern __shared__ float sm[];
    float* Wsm = sm;
    float* hsm = sm + 4 * 64 * WP;
    float* bsm = hsm + 64 * EP;

    int tid = threadIdx.x;
    int nb0 = blockIdx.x * 64;

    const float* Ws[4] = {A1w, A2w, B1w, B2w};
    #pragma unroll
    for (int m = 0; m < 4; m++) {
        float* Wm = Wsm + m * 64 * WP;
        for (int i = tid; i < 1024; i += 256) {
            int k = i >> 4, c4 = 4 * (i & 15);
            *(float4*)&Wm[wofs(k, c4)] = ((const float4*)Ws[m])[i];
        }
    }
    {
        const float* Bs[4] = {A1b, A2b, B1b, B2b};
        bsm[tid] = Bs[tid >> 6][tid & 63];
    }
    for (int i = tid; i < 64 * 16; i += 256) {
        int r = i >> 4, p = i & 15;
        int node = nb0 + r;
        float4 v = make_float4(0.f, 0.f, 0.f, 0.f);
        if (node < NN) v = ((const float4*)h)[node * 16 + p];
        *(float4*)&hsm[r * EP + 4 * p] = v;
    }
    if (tid < 64 && nb0 + tid < NN) g_deg[nb0 + tid] = 0;
    __syncthreads();

    int m = tid >> 6;
    int wloc = (tid >> 5) & 1;
    int lane = tid & 31;
    int g = lane >> 3, cg = lane & 7;
    int c0 = 8 * cg;
    int c0s = c0 + ((c0 & 32) >> 3);
    int rb = 32 * wloc + g;
    const float* Wm = Wsm + m * 64 * WP;

    ull acc[8][4];
    #pragma unroll
    for (int j = 0; j < 8; j++)
        #pragma unroll
        for (int c = 0; c < 4; c++) acc[j][c] = 0ull;

    #pragma unroll 2
    for (int k4 = 0; k4 < 16; k4++) {
        float4 a[8];
        #pragma unroll
        for (int j = 0; j < 8; j++)
            a[j] = *(const float4*)&hsm[(rb + 4 * j) * EP + 4 * k4];
        #pragma unroll
        for (int kk = 0; kk < 4; kk++) {
            const float* wr = &Wm[(4 * k4 + kk) * WP];
            ulonglong2 wA = *(const ulonglong2*)&wr[c0s];
            ulonglong2 wB = *(const ulonglong2*)&wr[c0s + 4];
            #pragma unroll
            for (int j = 0; j < 8; j++) {
                float av = (kk == 0) ? a[j].x : (kk == 1) ? a[j].y : (kk == 2) ? a[j].z : a[j].w;
                ull ax = splat2(av);
                fma2(acc[j][0], ax, wA.x); fma2(acc[j][1], ax, wA.y);
                fma2(acc[j][2], ax, wB.x); fma2(acc[j][3], ax, wB.y);
            }
        }
    }

    float* Om = (m == 0) ? g_A1h : (m == 1) ? g_A2h : (m == 2) ? g_B1h : g_B2h;
    #pragma unroll
    for (int j = 0; j < 8; j++) {
        int node = nb0 + rb + 4 * j;
        if (node < NN) {
            float4 bia = *(const float4*)&bsm[m * 64 + c0];
            float4 bib = *(const float4*)&bsm[m * 64 + c0 + 4];
            float2 t0 = unpk(acc[j][0]), t1 = unpk(acc[j][1]);
            float2 t2 = unpk(acc[j][2]), t3 = unpk(acc[j][3]);
            float4* op = (float4*)&Om[(size_t)node * 64 + c0];
            op[0] = make_float4(t0.x + bia.x, t0.y + bia.y, t1.x + bia.z, t1.y + bia.w);
            op[1] = make_float4(t2.x + bib.x, t2.y + bib.y, t3.x + bib.z, t3.y + bib.w);
        }
    }
}

// ---------------- K2: padded-slot CSR scatter (packed int2) ---------------------
__global__ void k_scatter(const int* __restrict__ src, const int* __restrict__ dst) {
    int i = blockIdx.x * blockDim.x + threadIdx.x;
    if (i < NE) {
        int d = dst[i];
        int r = atomicAdd(&g_deg[d], 1);
        if (r < SLOT)
            g_slot[d * SLOT + r] = make_int2(i, src[i]);
    }
}

// ---------------- K3: prep W^T bf16 hi/lo ---------------------------------------
__global__ void k_prep(const float* __restrict__ B3w) {
    int i = blockIdx.x * blockDim.x + threadIdx.x;
    if (i < 4096) {
        int n = i >> 6, k = i & 63;
        float w = B3w[k * 64 + n];
        unsigned short hi, lo;
        cvt_hilo(w, hi, lo);
        g_WT_hi[i] = hi;     // [n][k]
        g_WT_lo[i] = lo;
    }
}

// ---------------- K4: edge kernel — A-from-global bf16-split MMA ----------------
// 128 edges/block, 256 threads (8 warps), warp-tile = 16 edges x 64 cols.
// Smem (55296 B → 3 blocks/SM):
//   [0:512) ssm  [512:1024) dsm  [1024:1792) b3s|gs|bbs
//   [2048:11264)  B_hi 64 x 72 bf16   [11264:20480) B_lo
//   [20480:55296) xsm 128 x 68 f32
// Phases: load B/meta | (sync) | frag-load e + cvt + MMA | frag->xsm | (sync)
//         | 2-thr/row: gather + bias + LN + residual + coalesced store.
#define MT 128
#define BPIT 72
#define XPIT 68
#define SM_SSM 0
#define SM_DSM 512
#define SM_PAR 1024
#define SM_BHI 2048
#define SM_BLO (SM_BHI + 64 * BPIT * 2)
#define SM_XSM (SM_BLO + 64 * BPIT * 2)
#define SM_EDGE (SM_XSM + 128 * XPIT * 4)

__global__ void __launch_bounds__(256, 3) k_edge(
    const float* __restrict__ e,
    const int* __restrict__ src, const int* __restrict__ dst,
    const float* __restrict__ B3b,
    const float* __restrict__ lng, const float* __restrict__ lnb,
    float* __restrict__ out_e)
{
    extern __shared__ char smc[];
    int tid = threadIdx.x;
    int e0 = blockIdx.x * MT;

    int* ssm = (int*)(smc + SM_SSM);
    int* dsm = (int*)(smc + SM_DSM);
    float* b3s = (float*)(smc + SM_PAR);
    float* gs  = b3s + 64;
    float* bbs = gs + 64;
    unsigned short* Bhi = (unsigned short*)(smc + SM_BHI);
    unsigned short* Blo = (unsigned short*)(smc + SM_BLO);
    float* xsm = (float*)(smc + SM_XSM);

    // ---- W^T bf16 hi/lo into smem; metadata ----
    for (int i = tid; i < 1024; i += 256) {
        int n = i >> 4, kq = (i & 15) * 4;
        *(uint2*)&Bhi[n * BPIT + kq] = ((const uint2*)g_WT_hi)[i];
        *(uint2*)&Blo[n * BPIT + kq] = ((const uint2*)g_WT_lo)[i];
    }
    if (tid < MT) {
        int eg = e0 + tid;
        ssm[tid] = (eg < NE) ? src[eg] : 0;
        dsm[tid] = (eg < NE) ? dst[eg] : 0;
    }
    if (tid < 64) { b3s[tid] = B3b[tid]; gs[tid] = lng[tid]; bbs[tid] = lnb[tid]; }
    __syncthreads();

    // ---- MMA with A fragments loaded from global + converted in regs ----
    int w = tid >> 5, lane = tid & 31;
    int row = lane >> 2, qk = (lane & 3) * 2;
    int rw = 16 * w;

    int r0g = e0 + rw + row, r1g = r0g + 8;
    bool ok0 = r0g < NE, ok1 = r1g < NE;
    const float* ep0 = e + (size_t)r0g * 64;
    const float* ep1 = e + (size_t)r1g * 64;
    const float2 z2 = make_float2(0.f, 0.f);

    float acc[8][4];
    #pragma unroll
    for (int nt = 0; nt < 8; nt++)
        #pragma unroll
        for (int c = 0; c < 4; c++) acc[nt][c] = 0.f;

    #pragma unroll
    for (int kc = 0; kc < 4; kc++) {
        int kb = kc * 16 + qk;
        float2 v0 = ok0 ? *(const float2*)(ep0 + kb)     : z2;
        float2 v1 = ok1 ? *(const float2*)(ep1 + kb)     : z2;
        float2 v2 = ok0 ? *(const float2*)(ep0 + kb + 8) : z2;
        float2 v3 = ok1 ? *(const float2*)(ep1 + kb + 8) : z2;
        uint32_t a0h, a0l, a1h, a1l, a2h, a2l, a3h, a3l;
        f2_hilo(v0, a0h, a0l); f2_hilo(v1, a1h, a1l);
        f2_hilo(v2, a2h, a2l); f2_hilo(v3, a3h, a3l);

        #pragma unroll
        for (int nt = 0; nt < 8; nt++) {
            int n = nt * 8 + row;
            uint32_t bh0 = *(const uint32_t*)&Bhi[n * BPIT + kb];
            uint32_t bh1 = *(const uint32_t*)&Bhi[n * BPIT + kb + 8];
            mma16816(acc[nt], a0h, a1h, a2h, a3h, bh0, bh1);
            uint32_t bl0 = *(const uint32_t*)&Blo[n * BPIT + kb];
            uint32_t bl1 = *(const uint32_t*)&Blo[n * BPIT + kb + 8];
            mma16816(acc[nt], a0h, a1h, a2h, a3h, bl0, bl1);
        }
        #pragma unroll
        for (int nt = 0; nt < 8; nt++) {
            int n = nt * 8 + row;
            uint32_t bh0 = *(const uint32_t*)&Bhi[n * BPIT + kb];
            uint32_t bh1 = *(const uint32_t*)&Bhi[n * BPIT + kb + 8];
            mma16816(acc[nt], a0l, a1l, a2l, a3l, bh0, bh1);
        }
    }

    // ---- write C fragments to xsm ----
    {
        int col = 2 * (lane & 3);
        #pragma unroll
        for (int nt = 0; nt < 8; nt++) {
            int c = nt * 8 + col;
            *(float2*)&xsm[(rw + row) * XPIT + c]     = make_float2(acc[nt][0], acc[nt][1]);
            *(float2*)&xsm[(rw + row + 8) * XPIT + c] = make_float2(acc[nt][2], acc[nt][3]);
        }
    }
    __syncthreads();

    // ---- fused epilogue: 2 threads/row — gather + bias + LN + residual + store --
    {
        int r = tid >> 1, half = tid & 1;
        int eg = e0 + r;
        int s = ssm[r], d = dsm[r];
        const float* b1p = g_B1h + (size_t)s * 64;
        const float* b2p = g_B2h + (size_t)d * 64;

        float x[32];
        float sA = 0.f, sQ = 0.f;
        #pragma unroll
        for (int p = 0; p < 8; p++) {
            int c = p * 8 + half * 4;
            float4 xv = *(float4*)&xsm[r * XPIT + c];
            float4 u = *(const float4*)(b1p + c);
            float4 v = *(const float4*)(b2p + c);
            float4 b = *(const float4*)&b3s[c];
            xv.x += u.x + v.x + b.x; xv.y += u.y + v.y + b.y;
            xv.z += u.z + v.z + b.z; xv.w += u.w + v.w + b.w;
            x[4 * p + 0] = xv.x; x[4 * p + 1] = xv.y;
            x[4 * p + 2] = xv.z; x[4 * p + 3] = xv.w;
            sA += xv.x + xv.y + xv.z + xv.w;
            sQ += xv.x * xv.x + xv.y * xv.y + xv.z * xv.z + xv.w * xv.w;
        }
        sA += __shfl_xor_sync(0xffffffffu, sA, 1);
        sQ += __shfl_xor_sync(0xffffffffu, sQ, 1);
        float mu = sA * 0.015625f;
        float var = sQ * 0.015625f - mu * mu;
        float rstd = rsqrtf(var + 1e-5f);

        if (eg < NE) {
            #pragma unroll
            for (int p = 0; p < 8; p++) {
                int c = p * 8 + half * 4;
                float4 gv = *(const float4*)&gs[c];
                float4 bv = *(const float4*)&bbs[c];
                float4 ev = *(const float4*)(e + (size_t)eg * 64 + c);
                float4 o;
                o.x = fmaxf((x[4 * p + 0] - mu) * rstd * gv.x + bv.x, 0.f) + ev.x;
                o.y = fmaxf((x[4 * p + 1] - mu) * rstd * gv.y + bv.y, 0.f) + ev.y;
                o.z = fmaxf((x[4 * p + 2] - mu) * rstd * gv.z + bv.z, 0.f) + ev.z;
                o.w = fmaxf((x[4 * p + 3] - mu) * rstd * gv.w + bv.w, 0.f) + ev.w;
                *(float4*)(out_e + (size_t)eg * 64 + c) = o;
            }
        }
    }
}

// ---------------- K5: gather-side aggregation + node LN/out ---------------------
__global__ void __launch_bounds__(256) k_node(
    const float* __restrict__ h,
    const float* __restrict__ lng, const float* __restrict__ lnb,
    const float* __restrict__ out_e, float* __restrict__ out_h)
{
    int wid = threadIdx.x >> 5, lane = threadIdx.x & 31;
    int n = blockIdx.x * 8 + wid;
    if (n >= NN) return;

    int deg = g_deg[n];
    if (deg > SLOT) deg = SLOT;
    const int2* slots = &g_slot[(size_t)n * SLOT];

    int kmax = deg < 32 ? deg : 32;
    int2 myslot = make_int2(0, 0);
    if (lane < kmax) myslot = slots[lane];

    float2 ah = make_float2(0.f, 0.f), as = make_float2(0.f, 0.f);

    float2 ej_c, a2_c;
    if (kmax > 0) {
        int eid0 = __shfl_sync(0xffffffffu, myslot.x, 0);
        int s0   = __shfl_sync(0xffffffffu, myslot.y, 0);
        ej_c = *(const float2*)&out_e[(size_t)eid0 * 64 + 2 * lane];
        a2_c = *(const float2*)&g_A2h[(size_t)s0 * 64 + 2 * lane];
    }
    for (int k = 0; k < kmax; k++) {
        float2 ej = ej_c, a2 = a2_c;
        if (k + 1 < kmax) {
            int eidn = __shfl_sync(0xffffffffu, myslot.x, k + 1);
            int sn   = __shfl_sync(0xffffffffu, myslot.y, k + 1);
            ej_c = *(const float2*)&out_e[(size_t)eidn * 64 + 2 * lane];
            a2_c = *(const float2*)&g_A2h[(size_t)sn * 64 + 2 * lane];
        }
        float2 sg;
        sg.x = __fdividef(1.f, 1.f + __expf(-ej.x));
        sg.y = __fdividef(1.f, 1.f + __expf(-ej.y));
        ah.x += a2.x * sg.x; ah.y += a2.y * sg.y;
        as.x += sg.x;        as.y += sg.y;
    }
    for (int k = 32; k < deg; k++) {
        int2 pr = slots[k];
        float2 ej = *(const float2*)&out_e[(size_t)pr.x * 64 + 2 * lane];
        float2 a2 = *(const float2*)&g_A2h[(size_t)pr.y * 64 + 2 * lane];
        float2 sg;
        sg.x = __fdividef(1.f, 1.f + __expf(-ej.x));
        sg.y = __fdividef(1.f, 1.f + __expf(-ej.y));
        ah.x += a2.x * sg.x; ah.y += a2.y * sg.y;
        as.x += sg.x;        as.y += sg.y;
    }

    float2 a1 = *(const float2*)&g_A1h[(size_t)n * 64 + 2 * lane];
    float2 x;
    x.x = a1.x + ah.x / (as.x + 1e-6f);
    x.y = a1.y + ah.y / (as.y + 1e-6f);

    float sA = x.x + x.y, sQ = x.x * x.x + x.y * x.y;
    #pragma unroll
    for (int off = 16; off; off >>= 1) {
        sA += __shfl_xor_sync(0xffffffffu, sA, off);
        sQ += __shfl_xor_sync(0xffffffffu, sQ, off);
    }
    float mu = sA * 0.015625f;
    float var = sQ * 0.015625f - mu * mu;
    float rstd = rsqrtf(var + 1e-5f);

    float2 g2 = *(const float2*)&lng[2 * lane];
    float2 b2 = *(const float2*)&lnb[2 * lane];
    float2 hr = *(const float2*)&h[(size_t)n * 64 + 2 * lane];
    float2 outv;
    outv.x = fmaxf((x.x - mu) * rstd * g2.x + b2.x, 0.f) + hr.x;
    outv.y = fmaxf((x.y - mu) * rstd * g2.y + b2.y, 0.f) + hr.y;
    *(float2*)&out_h[(size_t)n * 64 + 2 * lane] = outv;
}

// ---------------- launch ----------------
extern "C" void kernel_launch(void* const* d_in, const int* in_sizes, int n_in,
                              void* d_out, int out_size)
{
    const float* h   = (const float*)d_in[0];
    const float* e   = (const float*)d_in[1];
    const int*   src = (const int*)d_in[2];
    const int*   dst = (const int*)d_in[3];
    const float* A1w = (const float*)d_in[4];
    const float* A1b = (const float*)d_in[5];
    const float* A2w = (const float*)d_in[6];
    const float* A2b = (const float*)d_in[7];
    const float* B1w = (const float*)d_in[8];
    const float* B1b = (const float*)d_in[9];
    const float* B2w = (const float*)d_in[10];
    const float* B2b = (const float*)d_in[11];
    const float* B3w = (const float*)d_in[12];
    const float* B3b = (const float*)d_in[13];
    const float* lneg = (const float*)d_in[14];
    const float* lneb = (const float*)d_in[15];
    const float* lnhg = (const float*)d_in[16];
    const float* lnhb = (const float*)d_in[17];

    float* out_h = (float*)d_out;
    float* out_e = out_h + (size_t)NN * 64;

    cudaFuncSetAttribute(k_proj, cudaFuncAttributeMaxDynamicSharedMemorySize, PROJ_SMEM);
    cudaFuncSetAttribute(k_edge, cudaFuncAttributeMaxDynamicSharedMemorySize, SM_EDGE);

    k_proj<<<(NN + 63) / 64, 256, PROJ_SMEM>>>(h, A1w, A1b, A2w, A2b, B1w, B1b, B2w, B2b);
    k_scatter<<<(NE + 255) / 256, 256>>>(src, dst);
    k_prep<<<16, 256>>>(B3w);
    k_edge<<<(NE + MT - 1) / MT, 256, SM_EDGE>>>(e, src, dst, B3b, lneg, lneb, out_e);
    k_node<<<(NN + 7) / 8, 256>>>(h, lnhg, lnhb, out_e, out_h);
}

// round 9
// speedup vs baseline: 1.3509x; 1.1139x over previous
#include <cuda_runtime.h>
#include <cuda_bf16.h>
#include <cstdint>

#define NN 100000
#define NE 1000000
#define SLOT 128

// ---------------- scratch (static device globals; no allocation) ----------------
__device__ float g_P[(size_t)NN * 256];          // [node][A1h|A2h|B1h|B2h]
__device__ int g_deg[NN];
__device__ int2 g_slot[NN * SLOT];               // (eid, src)
__device__ __align__(16) uint4 g_B3pk[64 * 16];  // packed B3^T mma-frag quads
__device__ __align__(16) uint4 g_Wpk[256 * 16];  // packed [A1|A2|B1|B2]^T quads
__device__ float g_ball[256];                    // concatenated biases

static __device__ __forceinline__ void cvt_hilo(float x, unsigned short &hi, unsigned short &lo) {
    __nv_bfloat16 h = __float2bfloat16(x);
    float r = x - __bfloat162float(h);
    __nv_bfloat16 l = __float2bfloat16(r);
    hi = *reinterpret_cast<unsigned short*>(&h);
    lo = *reinterpret_cast<unsigned short*>(&l);
}
static __device__ __forceinline__ void f2_hilo(float2 v, uint32_t &hi, uint32_t &lo) {
    unsigned short h0, l0, h1, l1;
    cvt_hilo(v.x, h0, l0); cvt_hilo(v.y, h1, l1);
    hi = (uint32_t)h0 | ((uint32_t)h1 << 16);
    lo = (uint32_t)l0 | ((uint32_t)l1 << 16);
}
static __device__ __forceinline__ uint4 pack4(float w0, float w1, float w8, float w9) {
    unsigned short h0, l0, h1, l1, h8, l8, h9, l9;
    cvt_hilo(w0, h0, l0); cvt_hilo(w1, h1, l1);
    cvt_hilo(w8, h8, l8); cvt_hilo(w9, h9, l9);
    uint4 r;
    r.x = (uint32_t)h0 | ((uint32_t)h1 << 16);
    r.y = (uint32_t)h8 | ((uint32_t)h9 << 16);
    r.z = (uint32_t)l0 | ((uint32_t)l1 << 16);
    r.w = (uint32_t)l8 | ((uint32_t)l9 << 16);
    return r;
}
static __device__ __forceinline__ void mma16816(float* c, uint32_t a0, uint32_t a1,
                                                uint32_t a2, uint32_t a3,
                                                uint32_t b0, uint32_t b1) {
    asm volatile(
        "mma.sync.aligned.m16n8k16.row.col.f32.bf16.bf16.f32 "
        "{%0,%1,%2,%3}, {%4,%5,%6,%7}, {%8,%9}, {%0,%1,%2,%3};"
        : "+f"(c[0]), "+f"(c[1]), "+f"(c[2]), "+f"(c[3])
        : "r"(a0), "r"(a1), "r"(a2), "r"(a3), "r"(b0), "r"(b1));
}

// ---------------- K1: prep — packed tables, biases, zero deg --------------------
__global__ void k_prep(
    const float* __restrict__ A1w, const float* __restrict__ A2w,
    const float* __restrict__ B1w, const float* __restrict__ B2w,
    const float* __restrict__ B3w,
    const float* __restrict__ A1b, const float* __restrict__ A2b,
    const float* __restrict__ B1b, const float* __restrict__ B2b)
{
    int i = blockIdx.x * 256 + threadIdx.x;
    if (i < 1024) {                                  // B3 packed: n in [0,64)
        int n = i >> 4, kq = i & 15;
        int kc = kq >> 2, q = kq & 3, kb = kc * 16 + q * 2;
        g_B3pk[n * 16 + kq] = pack4(B3w[kb * 64 + n], B3w[(kb + 1) * 64 + n],
                                    B3w[(kb + 8) * 64 + n], B3w[(kb + 9) * 64 + n]);
    } else if (i < 5120) {                           // Wall packed: n in [0,256)
        int j = i - 1024;
        int n = j >> 4, kq = j & 15;
        int m = n >> 6, c = n & 63;
        const float* W = (m == 0) ? A1w : (m == 1) ? A2w : (m == 2) ? B1w : B2w;
        int kc = kq >> 2, q = kq & 3, kb = kc * 16 + q * 2;
        g_Wpk[n * 16 + kq] = pack4(W[kb * 64 + c], W[(kb + 1) * 64 + c],
                                   W[(kb + 8) * 64 + c], W[(kb + 9) * 64 + c]);
    } else if (i < 5376) {                           // biases
        int c = i - 5120;
        int m = c >> 6;
        const float* B = (m == 0) ? A1b : (m == 1) ? A2b : (m == 2) ? B1b : B2b;
        g_ball[c] = B[c & 63];
    } else if (i - 5376 < NN) {
        g_deg[i - 5376] = 0;
    }
}

// ---------------- K2: padded-slot CSR scatter (packed int2) ---------------------
__global__ void k_scatter(const int* __restrict__ src, const int* __restrict__ dst) {
    int i = blockIdx.x * blockDim.x + threadIdx.x;
    if (i < NE) {
        int d = dst[i];
        int r = atomicAdd(&g_deg[d], 1);
        if (r < SLOT)
            g_slot[d * SLOT + r] = make_int2(i, src[i]);
    }
}

// ---------------- K3: node projections via tensor cores -------------------------
// 64 nodes/block, 256 threads. Warp w: rows 16*(w&3)..+15, col-half (w>>2)*128.
// A frags from global h (reg hi/lo split); B frags via __ldg from packed table.
// No smem, no barriers. Out: g_P[node][256] with bias.
__global__ void __launch_bounds__(256, 2) k_projmma(const float* __restrict__ h)
{
    int tid = threadIdx.x, w = tid >> 5, lane = tid & 31;
    int rw = 16 * (w & 3), nbase = (w >> 2) * 128;
    int row = lane >> 2, qk = (lane & 3) * 2;
    int nb0 = blockIdx.x * 64;
    int r0 = nb0 + rw + row, r1 = r0 + 8;
    bool ok0 = r0 < NN, ok1 = r1 < NN;
    const float* hp0 = h + (size_t)r0 * 64;
    const float* hp1 = h + (size_t)r1 * 64;
    const float2 z2 = make_float2(0.f, 0.f);

    float acc[16][4];
    #pragma unroll
    for (int nt = 0; nt < 16; nt++)
        #pragma unroll
        for (int c = 0; c < 4; c++) acc[nt][c] = 0.f;

    #pragma unroll
    for (int kc = 0; kc < 4; kc++) {
        int kb = kc * 16 + qk;
        float2 v0 = ok0 ? *(const float2*)(hp0 + kb)     : z2;
        float2 v1 = ok1 ? *(const float2*)(hp1 + kb)     : z2;
        float2 v2 = ok0 ? *(const float2*)(hp0 + kb + 8) : z2;
        float2 v3 = ok1 ? *(const float2*)(hp1 + kb + 8) : z2;
        uint32_t a0h, a0l, a1h, a1l, a2h, a2l, a3h, a3l;
        f2_hilo(v0, a0h, a0l); f2_hilo(v1, a1h, a1l);
        f2_hilo(v2, a2h, a2l); f2_hilo(v3, a3h, a3l);

        #pragma unroll
        for (int nt = 0; nt < 16; nt++) {
            int n = nbase + nt * 8 + row;
            uint4 B = __ldg(&g_Wpk[n * 16 + kc * 4 + (lane & 3)]);
            mma16816(acc[nt], a0h, a1h, a2h, a3h, B.x, B.y);
            mma16816(acc[nt], a0h, a1h, a2h, a3h, B.z, B.w);
            mma16816(acc[nt], a0l, a1l, a2l, a3l, B.x, B.y);
        }
    }

    #pragma unroll
    for (int nt = 0; nt < 16; nt++) {
        int C = nbase + nt * 8 + 2 * (lane & 3);
        float2 b = *(const float2*)&g_ball[C];
        if (ok0)
            *(float2*)&g_P[(size_t)r0 * 256 + C] = make_float2(acc[nt][0] + b.x, acc[nt][1] + b.y);
        if (ok1)
            *(float2*)&g_P[(size_t)r1 * 256 + C] = make_float2(acc[nt][2] + b.x, acc[nt][3] + b.y);
    }
}

// ---------------- K4: edge kernel — packed-B LDS.128 MMA + fused epilogue -------
// 128 edges/block, 256 threads. Smem (~57KB → 3 blocks/SM):
//   [0:512) ssm [512:1024) dsm [1024:1792) b3s|gs|bbs
//   [2048:22528) Bpk 64 x 20 uint4 (pitch 20 → conflict-free LDS.128)
//   [22528:57344) xsm 128 x 68 f32
#define MT 128
#define PPIT 20
#define XPIT 68
#define SM_SSM 0
#define SM_DSM 512
#define SM_PAR 1024
#define SM_BPK 2048
#define SM_XSM (SM_BPK + 64 * PPIT * 16)
#define SM_EDGE (SM_XSM + 128 * XPIT * 4)

__global__ void __launch_bounds__(256, 3) k_edge(
    const float* __restrict__ e,
    const int* __restrict__ src, const int* __restrict__ dst,
    const float* __restrict__ B3b,
    const float* __restrict__ lng, const float* __restrict__ lnb,
    float* __restrict__ out_e)
{
    extern __shared__ char smc[];
    int tid = threadIdx.x;
    int e0 = blockIdx.x * MT;

    int* ssm = (int*)(smc + SM_SSM);
    int* dsm = (int*)(smc + SM_DSM);
    float* b3s = (float*)(smc + SM_PAR);
    float* gs  = b3s + 64;
    float* bbs = gs + 64;
    uint4* Bs = (uint4*)(smc + SM_BPK);
    float* xsm = (float*)(smc + SM_XSM);

    // ---- stage packed B + metadata ----
    for (int i = tid; i < 1024; i += 256) {
        int n = i >> 4, kq = i & 15;
        Bs[n * PPIT + kq] = g_B3pk[i];
    }
    if (tid < MT) {
        int eg = e0 + tid;
        ssm[tid] = (eg < NE) ? src[eg] : 0;
        dsm[tid] = (eg < NE) ? dst[eg] : 0;
    }
    if (tid < 64) { b3s[tid] = B3b[tid]; gs[tid] = lng[tid]; bbs[tid] = lnb[tid]; }
    __syncthreads();

    // ---- MMA: A frags from global + reg hi/lo cvt; B via one LDS.128 / (kc,nt) --
    int w = tid >> 5, lane = tid & 31;
    int row = lane >> 2, qk = (lane & 3) * 2;
    int rw = 16 * w;

    int r0g = e0 + rw + row, r1g = r0g + 8;
    bool ok0 = r0g < NE, ok1 = r1g < NE;
    const float* ep0 = e + (size_t)r0g * 64;
    const float* ep1 = e + (size_t)r1g * 64;
    const float2 z2 = make_float2(0.f, 0.f);

    float acc[8][4];
    #pragma unroll
    for (int nt = 0; nt < 8; nt++)
        #pragma unroll
        for (int c = 0; c < 4; c++) acc[nt][c] = 0.f;

    #pragma unroll
    for (int kc = 0; kc < 4; kc++) {
        int kb = kc * 16 + qk;
        float2 v0 = ok0 ? *(const float2*)(ep0 + kb)     : z2;
        float2 v1 = ok1 ? *(const float2*)(ep1 + kb)     : z2;
        float2 v2 = ok0 ? *(const float2*)(ep0 + kb + 8) : z2;
        float2 v3 = ok1 ? *(const float2*)(ep1 + kb + 8) : z2;
        uint32_t a0h, a0l, a1h, a1l, a2h, a2l, a3h, a3l;
        f2_hilo(v0, a0h, a0l); f2_hilo(v1, a1h, a1l);
        f2_hilo(v2, a2h, a2l); f2_hilo(v3, a3h, a3l);

        #pragma unroll
        for (int nt = 0; nt < 8; nt++) {
            uint4 B = Bs[(nt * 8 + row) * PPIT + kc * 4 + (lane & 3)];
            mma16816(acc[nt], a0h, a1h, a2h, a3h, B.x, B.y);
            mma16816(acc[nt], a0h, a1h, a2h, a3h, B.z, B.w);
            mma16816(acc[nt], a0l, a1l, a2l, a3l, B.x, B.y);
        }
    }

    // ---- write C fragments to xsm ----
    {
        int col = 2 * (lane & 3);
        #pragma unroll
        for (int nt = 0; nt < 8; nt++) {
            int c = nt * 8 + col;
            *(float2*)&xsm[(rw + row) * XPIT + c]     = make_float2(acc[nt][0], acc[nt][1]);
            *(float2*)&xsm[(rw + row + 8) * XPIT + c] = make_float2(acc[nt][2], acc[nt][3]);
        }
    }
    __syncthreads();

    // ---- fused epilogue: 2 threads/row — gather + bias + LN + residual + store --
    {
        int r = tid >> 1, half = tid & 1;
        int eg = e0 + r;
        int s = ssm[r], d = dsm[r];
        const float* b1p = g_P + (size_t)s * 256 + 128;
        const float* b2p = g_P + (size_t)d * 256 + 192;

        float x[32];
        float sA = 0.f, sQ = 0.f;
        #pragma unroll
        for (int p = 0; p < 8; p++) {
            int c = p * 8 + half * 4;
            float4 xv = *(float4*)&xsm[r * XPIT + c];
            float4 u = *(const float4*)(b1p + c);
            float4 v = *(const float4*)(b2p + c);
            float4 b = *(const float4*)&b3s[c];
            xv.x += u.x + v.x + b.x; xv.y += u.y + v.y + b.y;
            xv.z += u.z + v.z + b.z; xv.w += u.w + v.w + b.w;
            x[4 * p + 0] = xv.x; x[4 * p + 1] = xv.y;
            x[4 * p + 2] = xv.z; x[4 * p + 3] = xv.w;
            sA += xv.x + xv.y + xv.z + xv.w;
            sQ += xv.x * xv.x + xv.y * xv.y + xv.z * xv.z + xv.w * xv.w;
        }
        sA += __shfl_xor_sync(0xffffffffu, sA, 1);
        sQ += __shfl_xor_sync(0xffffffffu, sQ, 1);
        float mu = sA * 0.015625f;
        float var = sQ * 0.015625f - mu * mu;
        float rstd = rsqrtf(var + 1e-5f);

        if (eg < NE) {
            #pragma unroll
            for (int p = 0; p < 8; p++) {
                int c = p * 8 + half * 4;
                float4 gv = *(const float4*)&gs[c];
                float4 bv = *(const float4*)&bbs[c];
                float4 ev = *(const float4*)(e + (size_t)eg * 64 + c);
                float4 o;
                o.x = fmaxf((x[4 * p + 0] - mu) * rstd * gv.x + bv.x, 0.f) + ev.x;
                o.y = fmaxf((x[4 * p + 1] - mu) * rstd * gv.y + bv.y, 0.f) + ev.y;
                o.z = fmaxf((x[4 * p + 2] - mu) * rstd * gv.z + bv.z, 0.f) + ev.z;
                o.w = fmaxf((x[4 * p + 3] - mu) * rstd * gv.w + bv.w, 0.f) + ev.w;
                *(float4*)(out_e + (size_t)eg * 64 + c) = o;
            }
        }
    }
}

// ---------------- K5: gather-side aggregation + node LN/out ---------------------
__global__ void __launch_bounds__(256) k_node(
    const float* __restrict__ h,
    const float* __restrict__ lng, const float* __restrict__ lnb,
    const float* __restrict__ out_e, float* __restrict__ out_h)
{
    int wid = threadIdx.x >> 5, lane = threadIdx.x & 31;
    int n = blockIdx.x * 8 + wid;
    if (n >= NN) return;

    int deg = g_deg[n];
    if (deg > SLOT) deg = SLOT;
    const int2* slots = &g_slot[(size_t)n * SLOT];

    int kmax = deg < 32 ? deg : 32;
    int2 sl = make_int2(0, 0);
    if (lane < kmax) sl = slots[lane];

    float2 ah = make_float2(0.f, 0.f), as_ = make_float2(0.f, 0.f);

    float2 e0v, a0v, e1v, a1v;
    if (kmax > 0) {
        int eid = __shfl_sync(0xffffffffu, sl.x, 0);
        int s   = __shfl_sync(0xffffffffu, sl.y, 0);
        e0v = *(const float2*)&out_e[(size_t)eid * 64 + 2 * lane];
        a0v = *(const float2*)&g_P[(size_t)s * 256 + 64 + 2 * lane];
    }
    if (kmax > 1) {
        int eid = __shfl_sync(0xffffffffu, sl.x, 1);
        int s   = __shfl_sync(0xffffffffu, sl.y, 1);
        e1v = *(const float2*)&out_e[(size_t)eid * 64 + 2 * lane];
        a1v = *(const float2*)&g_P[(size_t)s * 256 + 64 + 2 * lane];
    }

    int k = 0;
    for (; k + 2 <= kmax; k += 2) {
        float2 ce = e0v, ca = a0v;
        if (k + 2 < kmax) {
            int eid = __shfl_sync(0xffffffffu, sl.x, k + 2);
            int s   = __shfl_sync(0xffffffffu, sl.y, k + 2);
            e0v = *(const float2*)&out_e[(size_t)eid * 64 + 2 * lane];
            a0v = *(const float2*)&g_P[(size_t)s * 256 + 64 + 2 * lane];
        }
        float2 sg;
        sg.x = __fdividef(1.f, 1.f + __expf(-ce.x));
        sg.y = __fdividef(1.f, 1.f + __expf(-ce.y));
        ah.x += ca.x * sg.x; ah.y += ca.y * sg.y;
        as_.x += sg.x;       as_.y += sg.y;

        float2 ce1 = e1v, ca1 = a1v;
        if (k + 3 < kmax) {
            int eid = __shfl_sync(0xffffffffu, sl.x, k + 3);
            int s   = __shfl_sync(0xffffffffu, sl.y, k + 3);
            e1v = *(const float2*)&out_e[(size_t)eid * 64 + 2 * lane];
            a1v = *(const float2*)&g_P[(size_t)s * 256 + 64 + 2 * lane];
        }
        float2 sg1;
        sg1.x = __fdividef(1.f, 1.f + __expf(-ce1.x));
        sg1.y = __fdividef(1.f, 1.f + __expf(-ce1.y));
        ah.x += ca1.x * sg1.x; ah.y += ca1.y * sg1.y;
        as_.x += sg1.x;        as_.y += sg1.y;
    }
    if (k < kmax) {
        float2 sg;
        sg.x = __fdividef(1.f, 1.f + __expf(-e0v.x));
        sg.y = __fdividef(1.f, 1.f + __expf(-e0v.y));
        ah.x += a0v.x * sg.x; ah.y += a0v.y * sg.y;
        as_.x += sg.x;        as_.y += sg.y;
    }
    for (int kk = 32; kk < deg; kk++) {
        int2 pr = slots[kk];
        float2 ej = *(const float2*)&out_e[(size_t)pr.x * 64 + 2 * lane];
        float2 a2 = *(const float2*)&g_P[(size_t)pr.y * 256 + 64 + 2 * lane];
        float2 sg;
        sg.x = __fdividef(1.f, 1.f + __expf(-ej.x));
        sg.y = __fdividef(1.f, 1.f + __expf(-ej.y));
        ah.x += a2.x * sg.x; ah.y += a2.y * sg.y;
        as_.x += sg.x;       as_.y += sg.y;
    }

    float2 a1 = *(const float2*)&g_P[(size_t)n * 256 + 2 * lane];
    float2 x;
    x.x = a1.x + ah.x / (as_.x + 1e-6f);
    x.y = a1.y + ah.y / (as_.y + 1e-6f);

    float sA = x.x + x.y, sQ = x.x * x.x + x.y * x.y;
    #pragma unroll
    for (int off = 16; off; off >>= 1) {
        sA += __shfl_xor_sync(0xffffffffu, sA, off);
        sQ += __shfl_xor_sync(0xffffffffu, sQ, off);
    }
    float mu = sA * 0.015625f;
    float var = sQ * 0.015625f - mu * mu;
    float rstd = rsqrtf(var + 1e-5f);

    float2 g2 = *(const float2*)&lng[2 * lane];
    float2 b2 = *(const float2*)&lnb[2 * lane];
    float2 hr = *(const float2*)&h[(size_t)n * 64 + 2 * lane];
    float2 outv;
    outv.x = fmaxf((x.x - mu) * rstd * g2.x + b2.x, 0.f) + hr.x;
    outv.y = fmaxf((x.y - mu) * rstd * g2.y + b2.y, 0.f) + hr.y;
    *(float2*)&out_h[(size_t)n * 64 + 2 * lane] = outv;
}

// ---------------- launch ----------------
extern "C" void kernel_launch(void* const* d_in, const int* in_sizes, int n_in,
                              void* d_out, int out_size)
{
    const float* h   = (const float*)d_in[0];
    const float* e   = (const float*)d_in[1];
    const int*   src = (const int*)d_in[2];
    const int*   dst = (const int*)d_in[3];
    const float* A1w = (const float*)d_in[4];
    const float* A1b = (const float*)d_in[5];
    const float* A2w = (const float*)d_in[6];
    const float* A2b = (const float*)d_in[7];
    const float* B1w = (const float*)d_in[8];
    const float* B1b = (const float*)d_in[9];
    const float* B2w = (const float*)d_in[10];
    const float* B2b = (const float*)d_in[11];
    const float* B3w = (const float*)d_in[12];
    const float* B3b = (const float*)d_in[13];
    const float* lneg = (const float*)d_in[14];
    const float* lneb = (const float*)d_in[15];
    const float* lnhg = (const float*)d_in[16];
    const float* lnhb = (const float*)d_in[17];

    float* out_h = (float*)d_out;
    float* out_e = out_h + (size_t)NN * 64;

    cudaFuncSetAttribute(k_edge, cudaFuncAttributeMaxDynamicSharedMemorySize, SM_EDGE);

    k_prep<<<(5376 + NN + 255) / 256, 256>>>(A1w, A2w, B1w, B2w, B3w, A1b, A2b, B1b, B2b);
    k_scatter<<<(NE + 255) / 256, 256>>>(src, dst);
    k_projmma<<<(NN + 63) / 64, 256>>>(h);
    k_edge<<<(NE + MT - 1) / MT, 256, SM_EDGE>>>(e, src, dst, B3b, lneg, lneb, out_e);
    k_node<<<(NN + 7) / 8, 256>>>(h, lnhg, lnhb, out_e, out_h);
}